// round 2
// baseline (speedup 1.0000x reference)
#include <cuda_runtime.h>
#include <math.h>

#define NPTS 65536
#define KNN  16
#define DCH  96
#define HCH  384
#define HD   256

// ---------------- scratch (allocation-free: device globals) ----------------
__device__ float g_f[(size_t)NPTS * DCH];   // running feature [N,96]
__device__ float g_y[(size_t)NPTS * DCH];   // LFP projection scratch [N,96]
__device__ float g_h[(size_t)NPTS * HCH];   // MLP hidden scratch [N,384]

__device__ __forceinline__ float gelu_exact(float v) {
    return 0.5f * v * (1.0f + erff(v * 0.70710678118654752440f));
}

// ---------------- neighbor embedding: per-edge MLP + 16-way max ----------------
// 128 threads/block = 8 points x 16 edges. Each thread runs the 7->16->32->96
// MLP for one edge; channels computed in 3 chunks of 32 with a 16-lane
// butterfly max reduction.
__global__ void nbr_embed_kernel(
    const float* __restrict__ x, const float* __restrict__ xyz,
    const int* __restrict__ knn,
    const float* __restrict__ w1, const float* __restrict__ g1, const float* __restrict__ b1,
    const float* __restrict__ w2, const float* __restrict__ g2, const float* __restrict__ b2,
    const float* __restrict__ w3,
    const float* __restrict__ ng, const float* __restrict__ nb,
    float* __restrict__ f)
{
    __shared__ float sw1[7 * 16];
    __shared__ float sg1[16], sb1[16];
    __shared__ float sw2[16 * 32];
    __shared__ float sg2[32], sb2[32];
    __shared__ float sw3[32 * 96];
    __shared__ float sng[96], snb[96];

    const int tid = threadIdx.x;
    for (int i = tid; i < 7 * 16; i += 128) sw1[i] = w1[i];
    if (tid < 16) { sg1[tid] = g1[tid]; sb1[tid] = b1[tid]; }
    for (int i = tid; i < 16 * 32; i += 128) sw2[i] = w2[i];
    if (tid < 32) { sg2[tid] = g2[tid]; sb2[tid] = b2[tid]; }
    for (int i = tid; i < 32 * 96; i += 128) sw3[i] = w3[i];
    if (tid < 96) { sng[tid] = ng[tid]; snb[tid] = nb[tid]; }
    __syncthreads();

    const int n = blockIdx.x * 8 + (tid >> 4);
    const int k = tid & 15;
    const int j = knn[n * KNN + k];

    float v[7];
    v[0] = xyz[j * 3 + 0] - xyz[n * 3 + 0];
    v[1] = xyz[j * 3 + 1] - xyz[n * 3 + 1];
    v[2] = xyz[j * 3 + 2] - xyz[n * 3 + 2];
    v[3] = x[j * 4 + 0];
    v[4] = x[j * 4 + 1];
    v[5] = x[j * 4 + 2];
    v[6] = x[j * 4 + 3];

    float h1[16];
#pragma unroll
    for (int o = 0; o < 16; o++) {
        float s = 0.f;
#pragma unroll
        for (int i = 0; i < 7; i++) s += v[i] * sw1[i * 16 + o];
        h1[o] = gelu_exact(s * sg1[o] + sb1[o]);
    }

    float h2[32];
#pragma unroll
    for (int o = 0; o < 32; o++) {
        float s = 0.f;
#pragma unroll
        for (int i = 0; i < 16; i++) s += h1[i] * sw2[i * 32 + o];
        h2[o] = gelu_exact(s * sg2[o] + sb2[o]);
    }

#pragma unroll
    for (int ch = 0; ch < 3; ch++) {
        float acc[32];
#pragma unroll
        for (int o = 0; o < 32; o++) acc[o] = 0.f;
#pragma unroll
        for (int i = 0; i < 32; i++) {
            const float hv = h2[i];
#pragma unroll
            for (int o = 0; o < 32; o++) acc[o] += hv * sw3[i * 96 + ch * 32 + o];
        }
        // 16-lane butterfly max (stays within each 16-lane edge group)
#pragma unroll
        for (int off = 8; off >= 1; off >>= 1) {
#pragma unroll
            for (int o = 0; o < 32; o++)
                acc[o] = fmaxf(acc[o], __shfl_xor_sync(0xffffffffu, acc[o], off));
        }
        if (k == 0) {
#pragma unroll
            for (int o = 0; o < 32; o++) {
                const int c = ch * 32 + o;
                f[(size_t)n * DCH + c] = acc[o] * sng[c] + snb[c];
            }
        }
    }
}

// ---------------- generic tiled GEMM, C[M,Nc] = epi(A[M,K] @ W[K,Nc]) ----------------
// EPI: 0 = plain; 1 = gelu(acc + bias[n]); 2 = C += acc*g[n] + b[n] (residual-BN)
// ABN: apply a = a*gA[k] + bA[k] on A load (folds the head BN into the GEMM)
// Tile: BM=128, BN=32, BK=32, 128 threads, each thread 8x4 outputs.
// Requires M%128==0, K%32==0, Nc%32==0 (true for all shapes here).
template <int EPI, bool ABN>
__global__ void gemm128x32(
    const float* __restrict__ A, const float* __restrict__ W,
    float* __restrict__ C,
    const float* __restrict__ e1, const float* __restrict__ e2,
    const float* __restrict__ gA, const float* __restrict__ bA,
    int M, int K, int Nc)
{
    constexpr int BM = 128, BN = 32, BK = 32;
    __shared__ float As[BM][BK + 1];
    __shared__ float Ws[BK][BN];

    const int tid = threadIdx.x;            // 128
    const int m0 = blockIdx.y * BM;
    const int n0 = blockIdx.x * BN;
    const int ty = tid >> 3;                 // 0..15  (m group)
    const int tx = tid & 7;                  // 0..7   (n group)

    float acc[8][4];
#pragma unroll
    for (int i = 0; i < 8; i++)
#pragma unroll
        for (int jj = 0; jj < 4; jj++) acc[i][jj] = 0.f;

    for (int k0 = 0; k0 < K; k0 += BK) {
        // A tile: 128x32, coalesced over k
#pragma unroll
        for (int i = 0; i < 32; i++) {
            const int e = i * 128 + tid;
            const int m = e >> 5, kk = e & 31;
            float a = A[(size_t)(m0 + m) * K + (k0 + kk)];
            if (ABN) a = a * gA[k0 + kk] + bA[k0 + kk];
            As[m][kk] = a;
        }
        // W tile: 32x32, coalesced over n
#pragma unroll
        for (int i = 0; i < 8; i++) {
            const int e = i * 128 + tid;
            const int kk = e >> 5, nn = e & 31;
            Ws[kk][nn] = W[(size_t)(k0 + kk) * Nc + (n0 + nn)];
        }
        __syncthreads();

#pragma unroll
        for (int kk = 0; kk < BK; kk++) {
            float a[8], w[4];
#pragma unroll
            for (int i = 0; i < 8; i++) a[i] = As[ty * 8 + i][kk];
#pragma unroll
            for (int jj = 0; jj < 4; jj++) w[jj] = Ws[kk][tx * 4 + jj];
#pragma unroll
            for (int i = 0; i < 8; i++)
#pragma unroll
                for (int jj = 0; jj < 4; jj++) acc[i][jj] += a[i] * w[jj];
        }
        __syncthreads();
    }

#pragma unroll
    for (int i = 0; i < 8; i++) {
        const int m = m0 + ty * 8 + i;
#pragma unroll
        for (int jj = 0; jj < 4; jj++) {
            const int nn = n0 + tx * 4 + jj;
            const size_t idx = (size_t)m * Nc + nn;
            float vv = acc[i][jj];
            if (EPI == 1)       vv = gelu_exact(vv + e1[nn]);
            else if (EPI == 2)  vv = C[idx] + vv * e1[nn] + e2[nn];
            C[idx] = vv;
        }
    }
}

// ---------------- LFP edge: f += bn(max_k y[knn[n,k]] - y[n]) ----------------
// one warp per point; lane handles channels c, c+32, c+64
__global__ void lfp_edge_kernel(
    const float* __restrict__ y, const int* __restrict__ knn,
    const float* __restrict__ g, const float* __restrict__ b,
    float* __restrict__ f)
{
    const int warp = (blockIdx.x * blockDim.x + threadIdx.x) >> 5;
    const int lane = threadIdx.x & 31;
    const int n = warp;

    float m0 = -3.402823466e38f, m1 = m0, m2 = m0;
#pragma unroll
    for (int k = 0; k < KNN; k++) {
        const int j = knn[n * KNN + k];
        const float* yr = y + (size_t)j * DCH;
        m0 = fmaxf(m0, yr[lane]);
        m1 = fmaxf(m1, yr[lane + 32]);
        m2 = fmaxf(m2, yr[lane + 64]);
    }
    const float* yn = y + (size_t)n * DCH;
    float* fn = f + (size_t)n * DCH;
    fn[lane]      += (m0 - yn[lane])      * g[lane]      + b[lane];
    fn[lane + 32] += (m1 - yn[lane + 32]) * g[lane + 32] + b[lane + 32];
    fn[lane + 64] += (m2 - yn[lane + 64]) * g[lane + 64] + b[lane + 64];
}

// ---------------- host ----------------
static inline void run_mlp(const float* fbuf, float* hbuf, float* fout,
                           const float* w1, const float* b1,
                           const float* w2, const float* g, const float* b)
{
    // h = gelu(f @ w1 + b1)   [N,384]
    gemm128x32<1, false><<<dim3(HCH / 32, NPTS / 128), 128>>>(
        fbuf, w1, hbuf, b1, nullptr, nullptr, nullptr, NPTS, DCH, HCH);
    // f += bn(h @ w2)
    gemm128x32<2, false><<<dim3(DCH / 32, NPTS / 128), 128>>>(
        hbuf, w2, fout, g, b, nullptr, nullptr, NPTS, HCH, DCH);
}

extern "C" void kernel_launch(void* const* d_in, const int* in_sizes, int n_in,
                              void* d_out, int out_size)
{
    const float* x      = (const float*)d_in[0];
    const float* xyz    = (const float*)d_in[1];
    const int*   knn    = (const int*)  d_in[2];
    const float* ne_w1  = (const float*)d_in[3];
    const float* ne_g1  = (const float*)d_in[4];
    const float* ne_b1  = (const float*)d_in[5];
    const float* ne_w2  = (const float*)d_in[6];
    const float* ne_g2  = (const float*)d_in[7];
    const float* ne_b2  = (const float*)d_in[8];
    const float* ne_w3  = (const float*)d_in[9];
    const float* nbr_g  = (const float*)d_in[10];
    const float* nbr_b  = (const float*)d_in[11];
    const float* m0_w1  = (const float*)d_in[12];
    const float* m0_b1  = (const float*)d_in[13];
    const float* m0_w2  = (const float*)d_in[14];
    const float* m0_g   = (const float*)d_in[15];
    const float* m0_b   = (const float*)d_in[16];
    const float* lfp_w  = (const float*)d_in[17];
    const float* lfp_g  = (const float*)d_in[18];
    const float* lfp_b  = (const float*)d_in[19];
    const float* ms_w1  = (const float*)d_in[20];
    const float* ms_b1  = (const float*)d_in[21];
    const float* ms_w2  = (const float*)d_in[22];
    const float* ms_g   = (const float*)d_in[23];
    const float* ms_b   = (const float*)d_in[24];
    const float* pp_g   = (const float*)d_in[25];
    const float* pp_b   = (const float*)d_in[26];
    const float* pp_w   = (const float*)d_in[27];
    float* out = (float*)d_out;

    float *f, *y, *h;
    cudaGetSymbolAddress((void**)&f, g_f);
    cudaGetSymbolAddress((void**)&y, g_y);
    cudaGetSymbolAddress((void**)&h, g_h);

    // stage 1: neighbor embedding -> f [N,96]
    nbr_embed_kernel<<<NPTS / 8, 128>>>(
        x, xyz, knn,
        ne_w1, ne_g1, ne_b1, ne_w2, ne_g2, ne_b2, ne_w3,
        nbr_g, nbr_b, f);

    // stage 2: f += mlp0(f)
    run_mlp(f, h, f, m0_w1, m0_b1, m0_w2, m0_g, m0_b);

    // stage 3: DEPTH=4 LFP blocks (+ MLP every 2nd)
    for (int i = 0; i < 4; i++) {
        // y = f @ lfp_w[i]
        gemm128x32<0, false><<<dim3(DCH / 32, NPTS / 128), 128>>>(
            f, lfp_w + (size_t)i * DCH * DCH, y,
            nullptr, nullptr, nullptr, nullptr, NPTS, DCH, DCH);
        // f += bn(max_k y[knn] - y)
        lfp_edge_kernel<<<NPTS / 8, 256>>>(
            y, knn, lfp_g + i * DCH, lfp_b + i * DCH, f);
        if (i & 1) {
            const int jj = i / 2;
            run_mlp(f, h, f,
                    ms_w1 + (size_t)jj * DCH * HCH, ms_b1 + (size_t)jj * HCH,
                    ms_w2 + (size_t)jj * HCH * DCH, ms_g + jj * DCH, ms_b + jj * DCH);
        }
    }

    // stage 4: out = bn(f) @ pp_w   (BN folded into A load)
    gemm128x32<0, true><<<dim3(HD / 32, NPTS / 128), 128>>>(
        f, pp_w, out, nullptr, nullptr, pp_g, pp_b, NPTS, DCH, HD);
}

// round 3
// speedup vs baseline: 1.0468x; 1.0468x over previous
#include <cuda_runtime.h>
#include <math.h>

#define NPTS 65536
#define KNN  16
#define DCH  96
#define HCH  384
#define HD   256

// ---------------- scratch (allocation-free: device globals) ----------------
__device__ float g_f[(size_t)NPTS * DCH];   // running feature [N,96]
__device__ float g_y[(size_t)NPTS * DCH];   // LFP projection scratch [N,96]
__device__ float g_h[(size_t)NPTS * HCH];   // MLP hidden scratch [N,384]

__device__ __forceinline__ float gelu_exact(float v) {
    return 0.5f * v * (1.0f + erff(v * 0.70710678118654752440f));
}

// ---------------- neighbor embedding: per-edge MLP + 16-way max ----------------
// 128 threads/block = 8 points x 16 edges. Each thread runs the 7->16->32->96
// MLP for one edge; channels computed in 3 chunks of 32 with a 16-lane
// butterfly max reduction.
__global__ void nbr_embed_kernel(
    const float* __restrict__ x, const float* __restrict__ xyz,
    const int* __restrict__ knn,
    const float* __restrict__ w1, const float* __restrict__ g1, const float* __restrict__ b1,
    const float* __restrict__ w2, const float* __restrict__ g2, const float* __restrict__ b2,
    const float* __restrict__ w3,
    const float* __restrict__ ng, const float* __restrict__ nb,
    float* __restrict__ f)
{
    __shared__ float sw1[7 * 16];
    __shared__ float sg1[16], sb1[16];
    __shared__ float sw2[16 * 32];
    __shared__ float sg2[32], sb2[32];
    __shared__ float sw3[32 * 96];
    __shared__ float sng[96], snb[96];

    const int tid = threadIdx.x;
    for (int i = tid; i < 7 * 16; i += 128) sw1[i] = w1[i];
    if (tid < 16) { sg1[tid] = g1[tid]; sb1[tid] = b1[tid]; }
    for (int i = tid; i < 16 * 32; i += 128) sw2[i] = w2[i];
    if (tid < 32) { sg2[tid] = g2[tid]; sb2[tid] = b2[tid]; }
    for (int i = tid; i < 32 * 96; i += 128) sw3[i] = w3[i];
    if (tid < 96) { sng[tid] = ng[tid]; snb[tid] = nb[tid]; }
    __syncthreads();

    const int n = blockIdx.x * 8 + (tid >> 4);
    const int k = tid & 15;
    const int j = knn[n * KNN + k];

    float v[7];
    v[0] = xyz[j * 3 + 0] - xyz[n * 3 + 0];
    v[1] = xyz[j * 3 + 1] - xyz[n * 3 + 1];
    v[2] = xyz[j * 3 + 2] - xyz[n * 3 + 2];
    v[3] = x[j * 4 + 0];
    v[4] = x[j * 4 + 1];
    v[5] = x[j * 4 + 2];
    v[6] = x[j * 4 + 3];

    float h1[16];
#pragma unroll
    for (int o = 0; o < 16; o++) {
        float s = 0.f;
#pragma unroll
        for (int i = 0; i < 7; i++) s += v[i] * sw1[i * 16 + o];
        h1[o] = gelu_exact(s * sg1[o] + sb1[o]);
    }

    float h2[32];
#pragma unroll
    for (int o = 0; o < 32; o++) {
        float s = 0.f;
#pragma unroll
        for (int i = 0; i < 16; i++) s += h1[i] * sw2[i * 32 + o];
        h2[o] = gelu_exact(s * sg2[o] + sb2[o]);
    }

#pragma unroll
    for (int ch = 0; ch < 3; ch++) {
        float acc[32];
#pragma unroll
        for (int o = 0; o < 32; o++) acc[o] = 0.f;
#pragma unroll
        for (int i = 0; i < 32; i++) {
            const float hv = h2[i];
#pragma unroll
            for (int o = 0; o < 32; o++) acc[o] += hv * sw3[i * 96 + ch * 32 + o];
        }
        // 16-lane butterfly max (stays within each 16-lane edge group)
#pragma unroll
        for (int off = 8; off >= 1; off >>= 1) {
#pragma unroll
            for (int o = 0; o < 32; o++)
                acc[o] = fmaxf(acc[o], __shfl_xor_sync(0xffffffffu, acc[o], off));
        }
        if (k == 0) {
#pragma unroll
            for (int o = 0; o < 32; o++) {
                const int c = ch * 32 + o;
                f[(size_t)n * DCH + c] = acc[o] * sng[c] + snb[c];
            }
        }
    }
}

// ---------------- generic tiled GEMM, C[M,Nc] = epi(A[M,K] @ W[K,Nc]) ----------------
// EPI: 0 = plain; 1 = gelu(acc + bias[n]); 2 = C += acc*g[n] + b[n] (residual-BN)
// ABN: apply a = a*gA[k] + bA[k] on A load (folds the head BN into the GEMM)
// Tile: BM=128, BN=32, BK=32, 128 threads, each thread 8x4 outputs.
// Requires M%128==0, K%32==0, Nc%32==0 (true for all shapes here).
template <int EPI, bool ABN>
__global__ void gemm128x32(
    const float* __restrict__ A, const float* __restrict__ W,
    float* __restrict__ C,
    const float* __restrict__ e1, const float* __restrict__ e2,
    const float* __restrict__ gA, const float* __restrict__ bA,
    int M, int K, int Nc)
{
    constexpr int BM = 128, BN = 32, BK = 32;
    __shared__ float As[BM][BK + 1];
    __shared__ float Ws[BK][BN];

    const int tid = threadIdx.x;            // 128
    const int m0 = blockIdx.y * BM;
    const int n0 = blockIdx.x * BN;
    const int ty = tid >> 3;                 // 0..15  (m group)
    const int tx = tid & 7;                  // 0..7   (n group)

    float acc[8][4];
#pragma unroll
    for (int i = 0; i < 8; i++)
#pragma unroll
        for (int jj = 0; jj < 4; jj++) acc[i][jj] = 0.f;

    for (int k0 = 0; k0 < K; k0 += BK) {
        // A tile: 128x32, coalesced over k
#pragma unroll
        for (int i = 0; i < 32; i++) {
            const int e = i * 128 + tid;
            const int m = e >> 5, kk = e & 31;
            float a = A[(size_t)(m0 + m) * K + (k0 + kk)];
            if (ABN) a = a * gA[k0 + kk] + bA[k0 + kk];
            As[m][kk] = a;
        }
        // W tile: 32x32, coalesced over n
#pragma unroll
        for (int i = 0; i < 8; i++) {
            const int e = i * 128 + tid;
            const int kk = e >> 5, nn = e & 31;
            Ws[kk][nn] = W[(size_t)(k0 + kk) * Nc + (n0 + nn)];
        }
        __syncthreads();

#pragma unroll
        for (int kk = 0; kk < BK; kk++) {
            float a[8], w[4];
#pragma unroll
            for (int i = 0; i < 8; i++) a[i] = As[ty * 8 + i][kk];
#pragma unroll
            for (int jj = 0; jj < 4; jj++) w[jj] = Ws[kk][tx * 4 + jj];
#pragma unroll
            for (int i = 0; i < 8; i++)
#pragma unroll
                for (int jj = 0; jj < 4; jj++) acc[i][jj] += a[i] * w[jj];
        }
        __syncthreads();
    }

#pragma unroll
    for (int i = 0; i < 8; i++) {
        const int m = m0 + ty * 8 + i;
#pragma unroll
        for (int jj = 0; jj < 4; jj++) {
            const int nn = n0 + tx * 4 + jj;
            const size_t idx = (size_t)m * Nc + nn;
            float vv = acc[i][jj];
            if (EPI == 1)       vv = gelu_exact(vv + e1[nn]);
            else if (EPI == 2)  vv = C[idx] + vv * e1[nn] + e2[nn];
            C[idx] = vv;
        }
    }
}

// ---------------- LFP edge: f += bn(max_k y[knn[n,k]] - y[n]) ----------------
// one warp per point; lane handles channels c, c+32, c+64
__global__ void lfp_edge_kernel(
    const float* __restrict__ y, const int* __restrict__ knn,
    const float* __restrict__ g, const float* __restrict__ b,
    float* __restrict__ f)
{
    const int warp = (blockIdx.x * blockDim.x + threadIdx.x) >> 5;
    const int lane = threadIdx.x & 31;
    const int n = warp;

    float m0 = -3.402823466e38f, m1 = m0, m2 = m0;
#pragma unroll
    for (int k = 0; k < KNN; k++) {
        const int j = knn[n * KNN + k];
        const float* yr = y + (size_t)j * DCH;
        m0 = fmaxf(m0, yr[lane]);
        m1 = fmaxf(m1, yr[lane + 32]);
        m2 = fmaxf(m2, yr[lane + 64]);
    }
    const float* yn = y + (size_t)n * DCH;
    float* fn = f + (size_t)n * DCH;
    fn[lane]      += (m0 - yn[lane])      * g[lane]      + b[lane];
    fn[lane + 32] += (m1 - yn[lane + 32]) * g[lane + 32] + b[lane + 32];
    fn[lane + 64] += (m2 - yn[lane + 64]) * g[lane + 64] + b[lane + 64];
}

// ---------------- host ----------------
static inline void run_mlp(const float* fbuf, float* hbuf, float* fout,
                           const float* w1, const float* b1,
                           const float* w2, const float* g, const float* b)
{
    // h = gelu(f @ w1 + b1)   [N,384]
    gemm128x32<1, false><<<dim3(HCH / 32, NPTS / 128), 128>>>(
        fbuf, w1, hbuf, b1, nullptr, nullptr, nullptr, NPTS, DCH, HCH);
    // f += bn(h @ w2)
    gemm128x32<2, false><<<dim3(DCH / 32, NPTS / 128), 128>>>(
        hbuf, w2, fout, g, b, nullptr, nullptr, NPTS, HCH, DCH);
}

extern "C" void kernel_launch(void* const* d_in, const int* in_sizes, int n_in,
                              void* d_out, int out_size)
{
    const float* x      = (const float*)d_in[0];
    const float* xyz    = (const float*)d_in[1];
    const int*   knn    = (const int*)  d_in[2];
    const float* ne_w1  = (const float*)d_in[3];
    const float* ne_g1  = (const float*)d_in[4];
    const float* ne_b1  = (const float*)d_in[5];
    const float* ne_w2  = (const float*)d_in[6];
    const float* ne_g2  = (const float*)d_in[7];
    const float* ne_b2  = (const float*)d_in[8];
    const float* ne_w3  = (const float*)d_in[9];
    const float* nbr_g  = (const float*)d_in[10];
    const float* nbr_b  = (const float*)d_in[11];
    const float* m0_w1  = (const float*)d_in[12];
    const float* m0_b1  = (const float*)d_in[13];
    const float* m0_w2  = (const float*)d_in[14];
    const float* m0_g   = (const float*)d_in[15];
    const float* m0_b   = (const float*)d_in[16];
    const float* lfp_w  = (const float*)d_in[17];
    const float* lfp_g  = (const float*)d_in[18];
    const float* lfp_b  = (const float*)d_in[19];
    const float* ms_w1  = (const float*)d_in[20];
    const float* ms_b1  = (const float*)d_in[21];
    const float* ms_w2  = (const float*)d_in[22];
    const float* ms_g   = (const float*)d_in[23];
    const float* ms_b   = (const float*)d_in[24];
    const float* pp_g   = (const float*)d_in[25];
    const float* pp_b   = (const float*)d_in[26];
    const float* pp_w   = (const float*)d_in[27];
    float* out = (float*)d_out;

    float *f, *y, *h;
    cudaGetSymbolAddress((void**)&f, g_f);
    cudaGetSymbolAddress((void**)&y, g_y);
    cudaGetSymbolAddress((void**)&h, g_h);

    // stage 1: neighbor embedding -> f [N,96]
    nbr_embed_kernel<<<NPTS / 8, 128>>>(
        x, xyz, knn,
        ne_w1, ne_g1, ne_b1, ne_w2, ne_g2, ne_b2, ne_w3,
        nbr_g, nbr_b, f);

    // stage 2: f += mlp0(f)
    run_mlp(f, h, f, m0_w1, m0_b1, m0_w2, m0_g, m0_b);

    // stage 3: DEPTH=4 LFP blocks (+ MLP every 2nd)
    for (int i = 0; i < 4; i++) {
        // y = f @ lfp_w[i]
        gemm128x32<0, false><<<dim3(DCH / 32, NPTS / 128), 128>>>(
            f, lfp_w + (size_t)i * DCH * DCH, y,
            nullptr, nullptr, nullptr, nullptr, NPTS, DCH, DCH);
        // f += bn(max_k y[knn] - y)
        lfp_edge_kernel<<<NPTS / 8, 256>>>(
            y, knn, lfp_g + i * DCH, lfp_b + i * DCH, f);
        if (i & 1) {
            const int jj = i / 2;
            run_mlp(f, h, f,
                    ms_w1 + (size_t)jj * DCH * HCH, ms_b1 + (size_t)jj * HCH,
                    ms_w2 + (size_t)jj * HCH * DCH, ms_g + jj * DCH, ms_b + jj * DCH);
        }
    }

    // stage 4: out = bn(f) @ pp_w   (BN folded into A load)
    gemm128x32<0, true><<<dim3(HD / 32, NPTS / 128), 128>>>(
        f, pp_w, out, nullptr, nullptr, pp_g, pp_b, NPTS, DCH, HD);
}

// round 5
// speedup vs baseline: 1.5516x; 1.4823x over previous
#include <cuda_runtime.h>
#include <cuda_bf16.h>
#include <math.h>
#include <stdint.h>

#define NPTS 65536
#define KNN  16
#define DCH  96
#define HCH  384
#define HD   256

// ---------------- scratch (allocation-free: device globals) ----------------
__device__ float g_f[(size_t)NPTS * DCH];   // running feature [N,96]
__device__ float g_y[(size_t)NPTS * DCH];   // LFP projection scratch [N,96]
__device__ float g_h[(size_t)NPTS * HCH];   // MLP hidden scratch [N,384]

// pre-converted weights: [Nc][K] bf16, hi/lo split (B^T layout, n-major rows)
// LFP 4x(96x96) | UP 3x(384x96) | DOWN 3x(96x384) | HEAD (256x96)
#define WOFF_LFP   0
#define WOFF_UP    36864
#define WOFF_DOWN  147456
#define WOFF_HEAD  258048
#define WTOTAL     282624
__device__ __nv_bfloat16 g_whi[WTOTAL];
__device__ __nv_bfloat16 g_wlo[WTOTAL];

__device__ __forceinline__ float gelu_exact(float v) {
    return 0.5f * v * (1.0f + erff(v * 0.70710678118654752440f));
}

// pack two floats into bf16x2 hi and lo (hi = rn(x), lo = rn(x - hi))
__device__ __forceinline__ void split2(float x, float y, uint32_t& hi, uint32_t& lo) {
    __nv_bfloat16 hx = __float2bfloat16(x), hy = __float2bfloat16(y);
    __nv_bfloat16 lx = __float2bfloat16(x - __bfloat162float(hx));
    __nv_bfloat16 ly = __float2bfloat16(y - __bfloat162float(hy));
    hi = (uint32_t)__bfloat16_as_ushort(hx) | ((uint32_t)__bfloat16_as_ushort(hy) << 16);
    lo = (uint32_t)__bfloat16_as_ushort(lx) | ((uint32_t)__bfloat16_as_ushort(ly) << 16);
}

__device__ __forceinline__ void mma16816(float* d, const uint32_t* a, const uint32_t* b) {
    asm volatile(
        "mma.sync.aligned.m16n8k16.row.col.f32.bf16.bf16.f32 "
        "{%0,%1,%2,%3}, {%4,%5,%6,%7}, {%8,%9}, {%0,%1,%2,%3};"
        : "+f"(d[0]), "+f"(d[1]), "+f"(d[2]), "+f"(d[3])
        : "r"(a[0]), "r"(a[1]), "r"(a[2]), "r"(a[3]), "r"(b[0]), "r"(b[1]));
}

// =============== weight pre-conversion: fp32 [K][Nc] -> bf16 hi/lo [Nc][K] ===============
__global__ void conv_weights(const float* __restrict__ lfp_w,
                             const float* __restrict__ m0_w1, const float* __restrict__ ms_w1,
                             const float* __restrict__ m0_w2, const float* __restrict__ ms_w2,
                             const float* __restrict__ pp_w)
{
    int idx = blockIdx.x * blockDim.x + threadIdx.x;
    if (idx >= WTOTAL) return;
    float v;
    if (idx < WOFF_UP) {                       // LFP: 4 x [96n][96k]
        int i = idx / 9216, r = idx % 9216, n = r / 96, k = r % 96;
        v = lfp_w[i * 9216 + k * 96 + n];
    } else if (idx < WOFF_DOWN) {              // UP: 3 x [384n][96k], src [96][384]
        int t = idx - WOFF_UP, j = t / 36864, r = t % 36864, n = r / 96, k = r % 96;
        const float* src = (j == 0) ? m0_w1 : (ms_w1 + (size_t)(j - 1) * 96 * 384);
        v = src[k * 384 + n];
    } else if (idx < WOFF_HEAD) {              // DOWN: 3 x [96n][384k], src [384][96]
        int t = idx - WOFF_DOWN, j = t / 36864, r = t % 36864, n = r / 384, k = r % 384;
        const float* src = (j == 0) ? m0_w2 : (ms_w2 + (size_t)(j - 1) * 384 * 96);
        v = src[k * 96 + n];
    } else {                                   // HEAD: [256n][96k], src [96][256]
        int t = idx - WOFF_HEAD, n = t / 96, k = t % 96;
        v = pp_w[k * 256 + n];
    }
    __nv_bfloat16 hi = __float2bfloat16(v);
    __nv_bfloat16 lo = __float2bfloat16(v - __bfloat162float(hi));
    g_whi[idx] = hi;
    g_wlo[idx] = lo;
}

// =============== HMMA GEMM: C[M,Nc] = epi(A[M,KTOT] @ W^T), tile 128 x NT ===============
// EPI: 0 plain; 1 gelu(acc + e1[n]); 2 C += acc*e1[n] + e2[n].  ABN: a = a*gA[k]+bA[k] on load.
// Whi/Wlo: [Nc][KTOT] bf16 (transposed). bf16 hi/lo split, 3 HMMA per fragment pair.
// 256 threads = 8 warps (2 M x 4 N). Warp: 64(M) x NT/4(N). mma m16n8k16.
template <int EPI, bool ABN, int NT, int KTOT>
__global__ void __launch_bounds__(256) hmma_gemm(
    const float* __restrict__ A,
    const __nv_bfloat16* __restrict__ Whi, const __nv_bfloat16* __restrict__ Wlo,
    float* __restrict__ C,
    const float* __restrict__ e1, const float* __restrict__ e2,
    const float* __restrict__ gA, const float* __restrict__ bA,
    int Nc)
{
    constexpr int WN  = NT / 4;      // warp N width (24 or 32)
    constexpr int NTL = WN / 8;      // n-tiles per warp (3 or 4)
    constexpr int AS  = 20;          // smem row stride in u32 (conflict-free for frag reads)

    __shared__ uint32_t Ah[128 * AS], Al[128 * AS];
    __shared__ uint32_t Bh[NT * AS],  Bl[NT * AS];

    const int tid = threadIdx.x, wid = tid >> 5, lane = tid & 31;
    const int g = lane >> 2, t = lane & 3;
    const int warp_m = wid >> 2, warp_n = wid & 3;
    const int m0 = blockIdx.y * 128, n0 = blockIdx.x * NT;

    float acc[4][NTL][4] = {};

    const float* Ablk = A + (size_t)m0 * KTOT;

    for (int kc = 0; kc < KTOT / 32; kc++) {
        const int kb = kc * 32;

        // ---- A chunk: 128 x 32 fp32 -> bf16x2 hi/lo smem ----
#pragma unroll
        for (int it = 0; it < 4; it++) {
            const int e = it * 256 + tid;          // 0..1023
            const int row = e >> 3, q = e & 7;     // q*4 = col in chunk
            const int col = q * 4;
            float4 v = *(const float4*)&Ablk[(size_t)row * KTOT + kb + col];
            if (ABN) {
                const int k = kb + col;
                v.x = v.x * gA[k]     + bA[k];
                v.y = v.y * gA[k + 1] + bA[k + 1];
                v.z = v.z * gA[k + 2] + bA[k + 2];
                v.w = v.w * gA[k + 3] + bA[k + 3];
            }
            uint32_t h0, l0, h1, l1;
            split2(v.x, v.y, h0, l0);
            split2(v.z, v.w, h1, l1);
            const int si = row * AS + q * 2;
            *(uint2*)&Ah[si] = make_uint2(h0, h1);
            *(uint2*)&Al[si] = make_uint2(l0, l1);
        }
        // ---- B chunk: NT x 32 bf16 (pre-split) -> smem ----
        for (int e = tid; e < NT * 4; e += 256) {
            const int row = e >> 2, q = e & 3;     // q*8 halves
            const size_t gi = (size_t)(n0 + row) * KTOT + kb + q * 8;
            uint4 vh = *(const uint4*)&Whi[gi];
            uint4 vl = *(const uint4*)&Wlo[gi];
            const int si = row * AS + q * 4;
            *(uint2*)&Bh[si]     = make_uint2(vh.x, vh.y);
            *(uint2*)&Bh[si + 2] = make_uint2(vh.z, vh.w);
            *(uint2*)&Bl[si]     = make_uint2(vl.x, vl.y);
            *(uint2*)&Bl[si + 2] = make_uint2(vl.z, vl.w);
        }
        __syncthreads();

        // ---- compute: 2 k16 steps ----
#pragma unroll
        for (int ks = 0; ks < 2; ks++) {
            uint32_t bh[NTL][2], bl[NTL][2];
#pragma unroll
            for (int j = 0; j < NTL; j++) {
                const int n = warp_n * WN + j * 8 + g;
                const int si = n * AS + ks * 8 + t;
                bh[j][0] = Bh[si]; bh[j][1] = Bh[si + 4];
                bl[j][0] = Bl[si]; bl[j][1] = Bl[si + 4];
            }
#pragma unroll
            for (int i = 0; i < 4; i++) {
                const int r0 = warp_m * 64 + i * 16 + g;
                const int s0 = r0 * AS + ks * 8 + t;
                const int s8 = s0 + 8 * AS;
                uint32_t ah[4] = { Ah[s0], Ah[s8], Ah[s0 + 4], Ah[s8 + 4] };
                uint32_t al[4] = { Al[s0], Al[s8], Al[s0 + 4], Al[s8 + 4] };
#pragma unroll
                for (int j = 0; j < NTL; j++) {
                    mma16816(acc[i][j], ah, bh[j]);
                    mma16816(acc[i][j], ah, bl[j]);
                    mma16816(acc[i][j], al, bh[j]);
                }
            }
        }
        __syncthreads();
    }

    // ---- epilogue: fragment layout (groupID rows, threadID col pairs) ----
#pragma unroll
    for (int i = 0; i < 4; i++) {
        const int rm = m0 + warp_m * 64 + i * 16 + g;
#pragma unroll
        for (int j = 0; j < NTL; j++) {
            const int n = n0 + warp_n * WN + j * 8 + t * 2;
            float* d = acc[i][j];
            float v0 = d[0], v1 = d[1], v2 = d[2], v3 = d[3];
            float* p0 = &C[(size_t)rm * Nc + n];
            float* p1 = &C[(size_t)(rm + 8) * Nc + n];
            if (EPI == 1) {
                const float b0 = e1[n], b1 = e1[n + 1];
                v0 = gelu_exact(v0 + b0); v1 = gelu_exact(v1 + b1);
                v2 = gelu_exact(v2 + b0); v3 = gelu_exact(v3 + b1);
            } else if (EPI == 2) {
                const float s0 = e1[n], s1 = e1[n + 1];
                const float q0 = e2[n], q1 = e2[n + 1];
                float2 c0 = *(float2*)p0;
                float2 c1 = *(float2*)p1;
                v0 = c0.x + v0 * s0 + q0; v1 = c0.y + v1 * s1 + q1;
                v2 = c1.x + v2 * s0 + q0; v3 = c1.y + v3 * s1 + q1;
            }
            *(float2*)p0 = make_float2(v0, v1);
            *(float2*)p1 = make_float2(v2, v3);
        }
    }
}

// ---------------- neighbor embedding: per-edge MLP + 16-way max ----------------
__global__ void nbr_embed_kernel(
    const float* __restrict__ x, const float* __restrict__ xyz,
    const int* __restrict__ knn,
    const float* __restrict__ w1, const float* __restrict__ g1, const float* __restrict__ b1,
    const float* __restrict__ w2, const float* __restrict__ g2, const float* __restrict__ b2,
    const float* __restrict__ w3,
    const float* __restrict__ ng, const float* __restrict__ nb,
    float* __restrict__ f)
{
    __shared__ float sw1[7 * 16];
    __shared__ float sg1[16], sb1[16];
    __shared__ float sw2[16 * 32];
    __shared__ float sg2[32], sb2[32];
    __shared__ float sw3[32 * 96];
    __shared__ float sng[96], snb[96];

    const int tid = threadIdx.x;
    for (int i = tid; i < 7 * 16; i += 128) sw1[i] = w1[i];
    if (tid < 16) { sg1[tid] = g1[tid]; sb1[tid] = b1[tid]; }
    for (int i = tid; i < 16 * 32; i += 128) sw2[i] = w2[i];
    if (tid < 32) { sg2[tid] = g2[tid]; sb2[tid] = b2[tid]; }
    for (int i = tid; i < 32 * 96; i += 128) sw3[i] = w3[i];
    if (tid < 96) { sng[tid] = ng[tid]; snb[tid] = nb[tid]; }
    __syncthreads();

    const int n = blockIdx.x * 8 + (tid >> 4);
    const int k = tid & 15;
    const int j = knn[n * KNN + k];

    float v[7];
    v[0] = xyz[j * 3 + 0] - xyz[n * 3 + 0];
    v[1] = xyz[j * 3 + 1] - xyz[n * 3 + 1];
    v[2] = xyz[j * 3 + 2] - xyz[n * 3 + 2];
    v[3] = x[j * 4 + 0];
    v[4] = x[j * 4 + 1];
    v[5] = x[j * 4 + 2];
    v[6] = x[j * 4 + 3];

    float h1[16];
#pragma unroll
    for (int o = 0; o < 16; o++) {
        float s = 0.f;
#pragma unroll
        for (int i = 0; i < 7; i++) s += v[i] * sw1[i * 16 + o];
        h1[o] = gelu_exact(s * sg1[o] + sb1[o]);
    }
    float h2[32];
#pragma unroll
    for (int o = 0; o < 32; o++) {
        float s = 0.f;
#pragma unroll
        for (int i = 0; i < 16; i++) s += h1[i] * sw2[i * 32 + o];
        h2[o] = gelu_exact(s * sg2[o] + sb2[o]);
    }
#pragma unroll
    for (int ch = 0; ch < 3; ch++) {
        float acc[32];
#pragma unroll
        for (int o = 0; o < 32; o++) acc[o] = 0.f;
#pragma unroll
        for (int i = 0; i < 32; i++) {
            const float hv = h2[i];
#pragma unroll
            for (int o = 0; o < 32; o++) acc[o] += hv * sw3[i * 96 + ch * 32 + o];
        }
#pragma unroll
        for (int off = 8; off >= 1; off >>= 1) {
#pragma unroll
            for (int o = 0; o < 32; o++)
                acc[o] = fmaxf(acc[o], __shfl_xor_sync(0xffffffffu, acc[o], off));
        }
        if (k == 0) {
#pragma unroll
            for (int o = 0; o < 32; o++) {
                const int c = ch * 32 + o;
                f[(size_t)n * DCH + c] = acc[o] * sng[c] + snb[c];
            }
        }
    }
}

// ---------------- LFP edge: f += bn(max_k y[knn[n,k]] - y[n]) ----------------
__global__ void lfp_edge_kernel(
    const float* __restrict__ y, const int* __restrict__ knn,
    const float* __restrict__ g, const float* __restrict__ b,
    float* __restrict__ f)
{
    const int warp = (blockIdx.x * blockDim.x + threadIdx.x) >> 5;
    const int lane = threadIdx.x & 31;
    const int n = warp;

    float m0 = -3.402823466e38f, m1 = m0, m2 = m0;
#pragma unroll
    for (int k = 0; k < KNN; k++) {
        const int j = knn[n * KNN + k];
        const float* yr = y + (size_t)j * DCH;
        m0 = fmaxf(m0, yr[lane]);
        m1 = fmaxf(m1, yr[lane + 32]);
        m2 = fmaxf(m2, yr[lane + 64]);
    }
    const float* yn = y + (size_t)n * DCH;
    float* fn = f + (size_t)n * DCH;
    fn[lane]      += (m0 - yn[lane])      * g[lane]      + b[lane];
    fn[lane + 32] += (m1 - yn[lane + 32]) * g[lane + 32] + b[lane + 32];
    fn[lane + 64] += (m2 - yn[lane + 64]) * g[lane + 64] + b[lane + 64];
}

// ---------------- host ----------------
extern "C" void kernel_launch(void* const* d_in, const int* in_sizes, int n_in,
                              void* d_out, int out_size)
{
    const float* x      = (const float*)d_in[0];
    const float* xyz    = (const float*)d_in[1];
    const int*   knn    = (const int*)  d_in[2];
    const float* ne_w1  = (const float*)d_in[3];
    const float* ne_g1  = (const float*)d_in[4];
    const float* ne_b1  = (const float*)d_in[5];
    const float* ne_w2  = (const float*)d_in[6];
    const float* ne_g2  = (const float*)d_in[7];
    const float* ne_b2  = (const float*)d_in[8];
    const float* ne_w3  = (const float*)d_in[9];
    const float* nbr_g  = (const float*)d_in[10];
    const float* nbr_b  = (const float*)d_in[11];
    const float* m0_w1  = (const float*)d_in[12];
    const float* m0_b1  = (const float*)d_in[13];
    const float* m0_w2  = (const float*)d_in[14];
    const float* m0_g   = (const float*)d_in[15];
    const float* m0_b   = (const float*)d_in[16];
    const float* lfp_w  = (const float*)d_in[17];
    const float* lfp_g  = (const float*)d_in[18];
    const float* lfp_b  = (const float*)d_in[19];
    const float* ms_w1  = (const float*)d_in[20];
    const float* ms_b1  = (const float*)d_in[21];
    const float* ms_w2  = (const float*)d_in[22];
    const float* ms_g   = (const float*)d_in[23];
    const float* ms_b   = (const float*)d_in[24];
    const float* pp_g   = (const float*)d_in[25];
    const float* pp_b   = (const float*)d_in[26];
    const float* pp_w   = (const float*)d_in[27];
    float* out = (float*)d_out;

    float *f, *y, *h;
    __nv_bfloat16 *whi, *wlo;
    cudaGetSymbolAddress((void**)&f, g_f);
    cudaGetSymbolAddress((void**)&y, g_y);
    cudaGetSymbolAddress((void**)&h, g_h);
    cudaGetSymbolAddress((void**)&whi, g_whi);
    cudaGetSymbolAddress((void**)&wlo, g_wlo);

    // weight pre-conversion (transpose + hi/lo split)
    conv_weights<<<(WTOTAL + 255) / 256, 256>>>(lfp_w, m0_w1, ms_w1, m0_w2, ms_w2, pp_w);

    // stage 1: neighbor embedding -> f [N,96]
    nbr_embed_kernel<<<NPTS / 8, 128>>>(
        x, xyz, knn, ne_w1, ne_g1, ne_b1, ne_w2, ne_g2, ne_b2, ne_w3, nbr_g, nbr_b, f);

    // stage 2 + 3: mlp0, then 4x LFP (+ MLP on odd)
    auto launch_mlp = [&](int j) {
        // h = gelu(f @ w1 + b1)   [N,384]
        hmma_gemm<1, false, 128, 96><<<dim3(HCH / 128, NPTS / 128), 256>>>(
            f, whi + WOFF_UP + (size_t)j * 36864, wlo + WOFF_UP + (size_t)j * 36864,
            h, (j == 0) ? m0_b1 : (ms_b1 + (size_t)(j - 1) * HCH), nullptr, nullptr, nullptr, HCH);
        // f += bn(h @ w2)
        hmma_gemm<2, false, 96, 384><<<dim3(1, NPTS / 128), 256>>>(
            h, whi + WOFF_DOWN + (size_t)j * 36864, wlo + WOFF_DOWN + (size_t)j * 36864,
            f, (j == 0) ? m0_g : (ms_g + (size_t)(j - 1) * DCH),
            (j == 0) ? m0_b : (ms_b + (size_t)(j - 1) * DCH), nullptr, nullptr, DCH);
    };

    launch_mlp(0);
    for (int i = 0; i < 4; i++) {
        // y = f @ lfp_w[i]
        hmma_gemm<0, false, 96, 96><<<dim3(1, NPTS / 128), 256>>>(
            f, whi + WOFF_LFP + (size_t)i * 9216, wlo + WOFF_LFP + (size_t)i * 9216,
            y, nullptr, nullptr, nullptr, nullptr, DCH);
        // f += bn(max_k y[knn] - y)
        lfp_edge_kernel<<<NPTS / 8, 256>>>(y, knn, lfp_g + i * DCH, lfp_b + i * DCH, f);
        if (i & 1) launch_mlp(1 + i / 2);
    }

    // stage 4: out = bn(f) @ pp_w (BN folded into A load)
    hmma_gemm<0, true, 128, 96><<<dim3(HD / 128, NPTS / 128), 256>>>(
        f, whi + WOFF_HEAD, wlo + WOFF_HEAD,
        out, nullptr, nullptr, pp_g, pp_b, HD);
}

// round 6
// speedup vs baseline: 1.7301x; 1.1150x over previous
#include <cuda_runtime.h>
#include <cuda_bf16.h>
#include <math.h>
#include <stdint.h>

#define NPTS 65536
#define KNN  16
#define DCH  96
#define HCH  384
#define HD   256

// ---------------- scratch (allocation-free: device globals) ----------------
__device__ float g_f[(size_t)NPTS * DCH];   // running feature [N,96]
__device__ float g_y[(size_t)NPTS * DCH];   // LFP projection scratch [N,96]
__device__ float g_h[(size_t)NPTS * HCH];   // MLP hidden scratch [N,384]

// pre-converted weights: [Nc][K] bf16, hi/lo split (B^T layout, n-major rows)
// LFP 4x(96x96) | UP 3x(384x96) | DOWN 3x(96x384) | HEAD (256x96)
#define WOFF_LFP   0
#define WOFF_UP    36864
#define WOFF_DOWN  147456
#define WOFF_HEAD  258048
#define WTOTAL     282624
__device__ __nv_bfloat16 g_whi[WTOTAL];
__device__ __nv_bfloat16 g_wlo[WTOTAL];

__device__ __forceinline__ float gelu_exact(float v) {
    return 0.5f * v * (1.0f + erff(v * 0.70710678118654752440f));
}

__device__ __forceinline__ uint32_t smem_u32(const void* p) {
    uint32_t a;
    asm("{ .reg .u64 t; cvta.to.shared.u64 t, %1; cvt.u32.u64 %0, t; }" : "=r"(a) : "l"(p));
    return a;
}

// pack two floats into bf16x2 hi and lo (hi = rn(x), lo = rn(x - hi))
__device__ __forceinline__ void split2(float x, float y, uint32_t& hi, uint32_t& lo) {
    __nv_bfloat16 hx = __float2bfloat16(x), hy = __float2bfloat16(y);
    __nv_bfloat16 lx = __float2bfloat16(x - __bfloat162float(hx));
    __nv_bfloat16 ly = __float2bfloat16(y - __bfloat162float(hy));
    hi = (uint32_t)__bfloat16_as_ushort(hx) | ((uint32_t)__bfloat16_as_ushort(hy) << 16);
    lo = (uint32_t)__bfloat16_as_ushort(lx) | ((uint32_t)__bfloat16_as_ushort(ly) << 16);
}

__device__ __forceinline__ void mma16816(float* d, const uint32_t* a, const uint32_t* b) {
    asm volatile(
        "mma.sync.aligned.m16n8k16.row.col.f32.bf16.bf16.f32 "
        "{%0,%1,%2,%3}, {%4,%5,%6,%7}, {%8,%9}, {%0,%1,%2,%3};"
        : "+f"(d[0]), "+f"(d[1]), "+f"(d[2]), "+f"(d[3])
        : "r"(a[0]), "r"(a[1]), "r"(a[2]), "r"(a[3]), "r"(b[0]), "r"(b[1]));
}

__device__ __forceinline__ void ldm_x4(uint32_t* r, uint32_t addr) {
    asm volatile("ldmatrix.sync.aligned.m8n8.x4.shared.b16 {%0,%1,%2,%3}, [%4];"
        : "=r"(r[0]), "=r"(r[1]), "=r"(r[2]), "=r"(r[3]) : "r"(addr));
}

// =============== weight pre-conversion: fp32 [K][Nc] -> bf16 hi/lo [Nc][K] ===============
__global__ void conv_weights(const float* __restrict__ lfp_w,
                             const float* __restrict__ m0_w1, const float* __restrict__ ms_w1,
                             const float* __restrict__ m0_w2, const float* __restrict__ ms_w2,
                             const float* __restrict__ pp_w)
{
    int idx = blockIdx.x * blockDim.x + threadIdx.x;
    if (idx >= WTOTAL) return;
    float v;
    if (idx < WOFF_UP) {                       // LFP: 4 x [96n][96k]
        int i = idx / 9216, r = idx % 9216, n = r / 96, k = r % 96;
        v = lfp_w[i * 9216 + k * 96 + n];
    } else if (idx < WOFF_DOWN) {              // UP: 3 x [384n][96k], src [96][384]
        int t = idx - WOFF_UP, j = t / 36864, r = t % 36864, n = r / 96, k = r % 96;
        const float* src = (j == 0) ? m0_w1 : (ms_w1 + (size_t)(j - 1) * 96 * 384);
        v = src[k * 384 + n];
    } else if (idx < WOFF_HEAD) {              // DOWN: 3 x [96n][384k], src [384][96]
        int t = idx - WOFF_DOWN, j = t / 36864, r = t % 36864, n = r / 384, k = r % 384;
        const float* src = (j == 0) ? m0_w2 : (ms_w2 + (size_t)(j - 1) * 384 * 96);
        v = src[k * 96 + n];
    } else {                                   // HEAD: [256n][96k], src [96][256]
        int t = idx - WOFF_HEAD, n = t / 96, k = t % 96;
        v = pp_w[k * 256 + n];
    }
    __nv_bfloat16 hi = __float2bfloat16(v);
    __nv_bfloat16 lo = __float2bfloat16(v - __bfloat162float(hi));
    g_whi[idx] = hi;
    g_wlo[idx] = lo;
}

// =============== HMMA GEMM: C[M,Nc] = epi(A[M,KTOT] @ W^T), tile 128 x NT ===============
// EPI: 0 plain; 1 gelu(acc + e1[n]); 2 C += acc*e1[n] + e2[n].  ABN: a = a*gA[k]+bA[k] on load.
// bf16 hi/lo split, 3 HMMA per fragment pair. ldmatrix fragment loads.
// Double-buffered k32 chunks, 1 syncthreads per chunk.
// 256 threads = 8 warps (2 M x 4 N). Warp: 64(M) x NT/4(N).
template <int EPI, bool ABN, int NT, int KTOT>
__global__ void __launch_bounds__(256, 2) hmma_gemm(
    const float* __restrict__ A,
    const __nv_bfloat16* __restrict__ Whi, const __nv_bfloat16* __restrict__ Wlo,
    float* __restrict__ C,
    const float* __restrict__ e1, const float* __restrict__ e2,
    const float* __restrict__ gA, const float* __restrict__ bA,
    int Nc)
{
    constexpr int WN   = NT / 4;       // warp N width (16 / 24 / 32)
    constexpr int NTL  = WN / 8;       // n-tiles per warp
    constexpr int AS   = 20;           // smem row stride in u32 (80B: ldmatrix conflict-free)
    constexpr int NC   = KTOT / 32;    // k chunks
    constexpr int ASZ  = 128 * AS;     // u32 per A plane
    constexpr int BSZ  = NT * AS;      // u32 per B plane
    constexpr int BUFU = 2 * ASZ + 2 * BSZ;   // u32 per buffer (Ah|Al|Bh|Bl)

    extern __shared__ uint32_t sm[];
    const uint32_t sb = smem_u32(sm);

    const int tid = threadIdx.x, wid = tid >> 5, lane = tid & 31;
    const int g = lane >> 2, t = lane & 3;
    const int warp_m = wid >> 2, warp_n = wid & 3;
    const int m0 = blockIdx.y * 128, n0 = blockIdx.x * NT;

    float acc[4][NTL][4] = {};
    const float* Ablk = A + (size_t)m0 * KTOT;

    // per-lane ldmatrix byte offsets within a buffer
    const uint32_t aoff = ((warp_m * 64 + (lane & 7) + ((lane >> 3) & 1) * 8) * AS + (lane >> 4) * 4) * 4;
    const uint32_t boff = ((warp_n * WN + (lane & 7)) * AS + (lane >> 3) * 4) * 4;

    auto load_chunk = [&](int kc, uint32_t* buf) {
        uint32_t* Ah = buf;
        uint32_t* Al = buf + ASZ;
        uint32_t* Bh = buf + 2 * ASZ;
        uint32_t* Bl = buf + 2 * ASZ + BSZ;
        const int kb = kc * 32;
#pragma unroll
        for (int it = 0; it < 4; it++) {
            const int e = it * 256 + tid;          // 0..1023
            const int row = e >> 3, q = e & 7, col = q * 4;
            float4 v = *(const float4*)&Ablk[(size_t)row * KTOT + kb + col];
            if (ABN) {
                const int k = kb + col;
                v.x = v.x * gA[k]     + bA[k];
                v.y = v.y * gA[k + 1] + bA[k + 1];
                v.z = v.z * gA[k + 2] + bA[k + 2];
                v.w = v.w * gA[k + 3] + bA[k + 3];
            }
            uint32_t h0, l0, h1, l1;
            split2(v.x, v.y, h0, l0);
            split2(v.z, v.w, h1, l1);
            const int si = row * AS + q * 2;
            *(uint2*)&Ah[si] = make_uint2(h0, h1);
            *(uint2*)&Al[si] = make_uint2(l0, l1);
        }
#pragma unroll
        for (int e = tid; e < NT * 4; e += 256) {
            const int row = e >> 2, q = e & 3;
            const size_t gi = (size_t)(n0 + row) * KTOT + kb + q * 8;
            uint4 vh = *(const uint4*)&Whi[gi];
            uint4 vl = *(const uint4*)&Wlo[gi];
            const int si = row * AS + q * 4;
            *(uint2*)&Bh[si]     = make_uint2(vh.x, vh.y);
            *(uint2*)&Bh[si + 2] = make_uint2(vh.z, vh.w);
            *(uint2*)&Bl[si]     = make_uint2(vl.x, vl.y);
            *(uint2*)&Bl[si + 2] = make_uint2(vl.z, vl.w);
        }
    };

    auto compute = [&](uint32_t bufbase) {
        const uint32_t ahB = bufbase + aoff;
        const uint32_t alB = bufbase + ASZ * 4 + aoff;
        const uint32_t bhB = bufbase + 2 * ASZ * 4 + boff;
        const uint32_t blB = bufbase + (2 * ASZ + BSZ) * 4 + boff;
        uint32_t bh[NTL][4], bl[NTL][4];
#pragma unroll
        for (int j = 0; j < NTL; j++) {
            ldm_x4(bh[j], bhB + j * 8 * AS * 4);   // 4 regs: k0-7,k8-15,k16-23,k24-31
            ldm_x4(bl[j], blB + j * 8 * AS * 4);
        }
#pragma unroll
        for (int ks = 0; ks < 2; ks++) {
#pragma unroll
            for (int i = 0; i < 4; i++) {
                uint32_t ah[4], al[4];
                ldm_x4(ah, ahB + (i * 16 * AS + ks * 8) * 4);
                ldm_x4(al, alB + (i * 16 * AS + ks * 8) * 4);
#pragma unroll
                for (int j = 0; j < NTL; j++) {
                    mma16816(acc[i][j], ah, &bh[j][ks * 2]);
                    mma16816(acc[i][j], ah, &bl[j][ks * 2]);
                    mma16816(acc[i][j], al, &bh[j][ks * 2]);
                }
            }
        }
    };

    load_chunk(0, sm);
    __syncthreads();
#pragma unroll
    for (int kc = 0; kc < NC; kc++) {
        if (kc + 1 < NC) load_chunk(kc + 1, sm + ((kc + 1) & 1) * BUFU);
        compute(sb + (uint32_t)(kc & 1) * BUFU * 4);
        __syncthreads();
    }

    // ---- epilogue: fragment layout (groupID rows, threadID col pairs) ----
#pragma unroll
    for (int i = 0; i < 4; i++) {
        const int rm = m0 + warp_m * 64 + i * 16 + g;
#pragma unroll
        for (int j = 0; j < NTL; j++) {
            const int n = n0 + warp_n * WN + j * 8 + t * 2;
            float* d = acc[i][j];
            float v0 = d[0], v1 = d[1], v2 = d[2], v3 = d[3];
            float* p0 = &C[(size_t)rm * Nc + n];
            float* p1 = &C[(size_t)(rm + 8) * Nc + n];
            if (EPI == 1) {
                const float b0 = e1[n], b1 = e1[n + 1];
                v0 = gelu_exact(v0 + b0); v1 = gelu_exact(v1 + b1);
                v2 = gelu_exact(v2 + b0); v3 = gelu_exact(v3 + b1);
            } else if (EPI == 2) {
                const float s0 = e1[n], s1 = e1[n + 1];
                const float q0 = e2[n], q1 = e2[n + 1];
                float2 c0 = *(float2*)p0;
                float2 c1 = *(float2*)p1;
                v0 = c0.x + v0 * s0 + q0; v1 = c0.y + v1 * s1 + q1;
                v2 = c1.x + v2 * s0 + q0; v3 = c1.y + v3 * s1 + q1;
            }
            *(float2*)p0 = make_float2(v0, v1);
            *(float2*)p1 = make_float2(v2, v3);
        }
    }
}

// ---------------- neighbor embedding: per-edge MLP + 16-way max ----------------
__global__ void nbr_embed_kernel(
    const float* __restrict__ x, const float* __restrict__ xyz,
    const int* __restrict__ knn,
    const float* __restrict__ w1, const float* __restrict__ g1, const float* __restrict__ b1,
    const float* __restrict__ w2, const float* __restrict__ g2, const float* __restrict__ b2,
    const float* __restrict__ w3,
    const float* __restrict__ ng, const float* __restrict__ nb,
    float* __restrict__ f)
{
    __shared__ float sw1[7 * 16];
    __shared__ float sg1[16], sb1[16];
    __shared__ float sw2[16 * 32];
    __shared__ float sg2[32], sb2[32];
    __shared__ float sw3[32 * 96];
    __shared__ float sng[96], snb[96];

    const int tid = threadIdx.x;
    for (int i = tid; i < 7 * 16; i += 128) sw1[i] = w1[i];
    if (tid < 16) { sg1[tid] = g1[tid]; sb1[tid] = b1[tid]; }
    for (int i = tid; i < 16 * 32; i += 128) sw2[i] = w2[i];
    if (tid < 32) { sg2[tid] = g2[tid]; sb2[tid] = b2[tid]; }
    for (int i = tid; i < 32 * 96; i += 128) sw3[i] = w3[i];
    if (tid < 96) { sng[tid] = ng[tid]; snb[tid] = nb[tid]; }
    __syncthreads();

    const int n = blockIdx.x * 8 + (tid >> 4);
    const int k = tid & 15;
    const int j = knn[n * KNN + k];

    float v[7];
    v[0] = xyz[j * 3 + 0] - xyz[n * 3 + 0];
    v[1] = xyz[j * 3 + 1] - xyz[n * 3 + 1];
    v[2] = xyz[j * 3 + 2] - xyz[n * 3 + 2];
    v[3] = x[j * 4 + 0];
    v[4] = x[j * 4 + 1];
    v[5] = x[j * 4 + 2];
    v[6] = x[j * 4 + 3];

    float h1[16];
#pragma unroll
    for (int o = 0; o < 16; o++) {
        float s = 0.f;
#pragma unroll
        for (int i = 0; i < 7; i++) s += v[i] * sw1[i * 16 + o];
        h1[o] = gelu_exact(s * sg1[o] + sb1[o]);
    }
    float h2[32];
#pragma unroll
    for (int o = 0; o < 32; o++) {
        float s = 0.f;
#pragma unroll
        for (int i = 0; i < 16; i++) s += h1[i] * sw2[i * 32 + o];
        h2[o] = gelu_exact(s * sg2[o] + sb2[o]);
    }
#pragma unroll
    for (int ch = 0; ch < 3; ch++) {
        float acc[32];
#pragma unroll
        for (int o = 0; o < 32; o++) acc[o] = 0.f;
#pragma unroll
        for (int i = 0; i < 32; i++) {
            const float hv = h2[i];
#pragma unroll
            for (int o = 0; o < 32; o++) acc[o] += hv * sw3[i * 96 + ch * 32 + o];
        }
#pragma unroll
        for (int off = 8; off >= 1; off >>= 1) {
#pragma unroll
            for (int o = 0; o < 32; o++)
                acc[o] = fmaxf(acc[o], __shfl_xor_sync(0xffffffffu, acc[o], off));
        }
        if (k == 0) {
#pragma unroll
            for (int o = 0; o < 32; o++) {
                const int c = ch * 32 + o;
                f[(size_t)n * DCH + c] = acc[o] * sng[c] + snb[c];
            }
        }
    }
}

// ---------------- LFP edge: f += bn(max_k y[knn[n,k]] - y[n]) ----------------
__global__ void lfp_edge_kernel(
    const float* __restrict__ y, const int* __restrict__ knn,
    const float* __restrict__ g, const float* __restrict__ b,
    float* __restrict__ f)
{
    const int warp = (blockIdx.x * blockDim.x + threadIdx.x) >> 5;
    const int lane = threadIdx.x & 31;
    const int n = warp;

    float m0 = -3.402823466e38f, m1 = m0, m2 = m0;
#pragma unroll
    for (int k = 0; k < KNN; k++) {
        const int j = knn[n * KNN + k];
        const float* yr = y + (size_t)j * DCH;
        m0 = fmaxf(m0, yr[lane]);
        m1 = fmaxf(m1, yr[lane + 32]);
        m2 = fmaxf(m2, yr[lane + 64]);
    }
    const float* yn = y + (size_t)n * DCH;
    float* fn = f + (size_t)n * DCH;
    fn[lane]      += (m0 - yn[lane])      * g[lane]      + b[lane];
    fn[lane + 32] += (m1 - yn[lane + 32]) * g[lane + 32] + b[lane + 32];
    fn[lane + 64] += (m2 - yn[lane + 64]) * g[lane + 64] + b[lane + 64];
}

// ---------------- host ----------------
// smem bytes: 2 buffers * (2*128*20 + 2*NT*20) u32 * 4B
static inline int smem_bytes(int NT) { return 2 * (2 * 128 * 20 + 2 * NT * 20) * 4; }

extern "C" void kernel_launch(void* const* d_in, const int* in_sizes, int n_in,
                              void* d_out, int out_size)
{
    const float* x      = (const float*)d_in[0];
    const float* xyz    = (const float*)d_in[1];
    const int*   knn    = (const int*)  d_in[2];
    const float* ne_w1  = (const float*)d_in[3];
    const float* ne_g1  = (const float*)d_in[4];
    const float* ne_b1  = (const float*)d_in[5];
    const float* ne_w2  = (const float*)d_in[6];
    const float* ne_g2  = (const float*)d_in[7];
    const float* ne_b2  = (const float*)d_in[8];
    const float* ne_w3  = (const float*)d_in[9];
    const float* nbr_g  = (const float*)d_in[10];
    const float* nbr_b  = (const float*)d_in[11];
    const float* m0_w1  = (const float*)d_in[12];
    const float* m0_b1  = (const float*)d_in[13];
    const float* m0_w2  = (const float*)d_in[14];
    const float* m0_g   = (const float*)d_in[15];
    const float* m0_b   = (const float*)d_in[16];
    const float* lfp_w  = (const float*)d_in[17];
    const float* lfp_g  = (const float*)d_in[18];
    const float* lfp_b  = (const float*)d_in[19];
    const float* ms_w1  = (const float*)d_in[20];
    const float* ms_b1  = (const float*)d_in[21];
    const float* ms_w2  = (const float*)d_in[22];
    const float* ms_g   = (const float*)d_in[23];
    const float* ms_b   = (const float*)d_in[24];
    const float* pp_g   = (const float*)d_in[25];
    const float* pp_b   = (const float*)d_in[26];
    const float* pp_w   = (const float*)d_in[27];
    float* out = (float*)d_out;

    float *f, *y, *h;
    __nv_bfloat16 *whi, *wlo;
    cudaGetSymbolAddress((void**)&f, g_f);
    cudaGetSymbolAddress((void**)&y, g_y);
    cudaGetSymbolAddress((void**)&h, g_h);
    cudaGetSymbolAddress((void**)&whi, g_whi);
    cudaGetSymbolAddress((void**)&wlo, g_wlo);

    const int SM96 = smem_bytes(96);   // 71680
    const int SM64 = smem_bytes(64);   // 61440
    cudaFuncSetAttribute(hmma_gemm<0, false, 96, 96>,  cudaFuncAttributeMaxDynamicSharedMemorySize, SM96);
    cudaFuncSetAttribute(hmma_gemm<1, false, 96, 96>,  cudaFuncAttributeMaxDynamicSharedMemorySize, SM96);
    cudaFuncSetAttribute(hmma_gemm<2, false, 96, 384>, cudaFuncAttributeMaxDynamicSharedMemorySize, SM96);
    cudaFuncSetAttribute(hmma_gemm<0, true, 64, 96>,   cudaFuncAttributeMaxDynamicSharedMemorySize, SM64);

    // weight pre-conversion (transpose + hi/lo split)
    conv_weights<<<(WTOTAL + 255) / 256, 256>>>(lfp_w, m0_w1, ms_w1, m0_w2, ms_w2, pp_w);

    // stage 1: neighbor embedding -> f [N,96]
    nbr_embed_kernel<<<NPTS / 8, 128>>>(
        x, xyz, knn, ne_w1, ne_g1, ne_b1, ne_w2, ne_g2, ne_b2, ne_w3, nbr_g, nbr_b, f);

    // stage 2 + 3: mlp0, then 4x LFP (+ MLP on odd)
    auto launch_mlp = [&](int j) {
        // h = gelu(f @ w1 + b1)   [N,384]
        hmma_gemm<1, false, 96, 96><<<dim3(HCH / 96, NPTS / 128), 256, SM96>>>(
            f, whi + WOFF_UP + (size_t)j * 36864, wlo + WOFF_UP + (size_t)j * 36864,
            h, (j == 0) ? m0_b1 : (ms_b1 + (size_t)(j - 1) * HCH), nullptr, nullptr, nullptr, HCH);
        // f += bn(h @ w2)
        hmma_gemm<2, false, 96, 384><<<dim3(1, NPTS / 128), 256, SM96>>>(
            h, whi + WOFF_DOWN + (size_t)j * 36864, wlo + WOFF_DOWN + (size_t)j * 36864,
            f, (j == 0) ? m0_g : (ms_g + (size_t)(j - 1) * DCH),
            (j == 0) ? m0_b : (ms_b + (size_t)(j - 1) * DCH), nullptr, nullptr, DCH);
    };

    launch_mlp(0);
    for (int i = 0; i < 4; i++) {
        // y = f @ lfp_w[i]
        hmma_gemm<0, false, 96, 96><<<dim3(1, NPTS / 128), 256, SM96>>>(
            f, whi + WOFF_LFP + (size_t)i * 9216, wlo + WOFF_LFP + (size_t)i * 9216,
            y, nullptr, nullptr, nullptr, nullptr, DCH);
        // f += bn(max_k y[knn] - y)
        lfp_edge_kernel<<<NPTS / 8, 256>>>(y, knn, lfp_g + i * DCH, lfp_b + i * DCH, f);
        if (i & 1) launch_mlp(1 + i / 2);
    }

    // stage 4: out = bn(f) @ pp_w (BN folded into A load)
    hmma_gemm<0, true, 64, 96><<<dim3(HD / 64, NPTS / 128), 256, SM64>>>(
        f, whi + WOFF_HEAD, wlo + WOFF_HEAD,
        out, nullptr, nullptr, pp_g, pp_b, HD);
}

// round 7
// speedup vs baseline: 1.7916x; 1.0355x over previous
#include <cuda_runtime.h>
#include <cuda_bf16.h>
#include <math.h>
#include <stdint.h>

#define NPTS 65536
#define KNN  16
#define DCH  96
#define HCH  384
#define HD   256

// ---------------- scratch (allocation-free: device globals) ----------------
__device__ float g_f[(size_t)NPTS * DCH];   // running feature [N,96]
__device__ float g_y[(size_t)NPTS * DCH];   // LFP projection scratch [N,96]

// pre-converted weights: [Nc][K] bf16, hi/lo split (B^T layout, n-major rows)
// LFP 4x(96x96) | UP 3x(384x96) | DOWN 3x(96x384) | HEAD (256x96)
#define WOFF_LFP   0
#define WOFF_UP    36864
#define WOFF_DOWN  147456
#define WOFF_HEAD  258048
#define WTOTAL     282624
__device__ __nv_bfloat16 g_whi[WTOTAL];
__device__ __nv_bfloat16 g_wlo[WTOTAL];

__device__ __forceinline__ float gelu_exact(float v) {
    return 0.5f * v * (1.0f + erff(v * 0.70710678118654752440f));
}

__device__ __forceinline__ uint32_t smem_u32(const void* p) {
    uint32_t a;
    asm("{ .reg .u64 t; cvta.to.shared.u64 t, %1; cvt.u32.u64 %0, t; }" : "=r"(a) : "l"(p));
    return a;
}

// pack two floats into bf16x2 hi and lo (hi = rn(x), lo = rn(x - hi))
__device__ __forceinline__ void split2(float x, float y, uint32_t& hi, uint32_t& lo) {
    __nv_bfloat16 hx = __float2bfloat16(x), hy = __float2bfloat16(y);
    __nv_bfloat16 lx = __float2bfloat16(x - __bfloat162float(hx));
    __nv_bfloat16 ly = __float2bfloat16(y - __bfloat162float(hy));
    hi = (uint32_t)__bfloat16_as_ushort(hx) | ((uint32_t)__bfloat16_as_ushort(hy) << 16);
    lo = (uint32_t)__bfloat16_as_ushort(lx) | ((uint32_t)__bfloat16_as_ushort(ly) << 16);
}

__device__ __forceinline__ void mma16816(float* d, const uint32_t* a, const uint32_t* b) {
    asm volatile(
        "mma.sync.aligned.m16n8k16.row.col.f32.bf16.bf16.f32 "
        "{%0,%1,%2,%3}, {%4,%5,%6,%7}, {%8,%9}, {%0,%1,%2,%3};"
        : "+f"(d[0]), "+f"(d[1]), "+f"(d[2]), "+f"(d[3])
        : "r"(a[0]), "r"(a[1]), "r"(a[2]), "r"(a[3]), "r"(b[0]), "r"(b[1]));
}

__device__ __forceinline__ void ldm_x4(uint32_t* r, uint32_t addr) {
    asm volatile("ldmatrix.sync.aligned.m8n8.x4.shared.b16 {%0,%1,%2,%3}, [%4];"
        : "=r"(r[0]), "=r"(r[1]), "=r"(r[2]), "=r"(r[3]) : "r"(addr));
}

// =============== weight pre-conversion: fp32 [K][Nc] -> bf16 hi/lo [Nc][K] ===============
__global__ void conv_weights(const float* __restrict__ lfp_w,
                             const float* __restrict__ m0_w1, const float* __restrict__ ms_w1,
                             const float* __restrict__ m0_w2, const float* __restrict__ ms_w2,
                             const float* __restrict__ pp_w)
{
    int idx = blockIdx.x * blockDim.x + threadIdx.x;
    if (idx >= WTOTAL) return;
    float v;
    if (idx < WOFF_UP) {                       // LFP: 4 x [96n][96k]
        int i = idx / 9216, r = idx % 9216, n = r / 96, k = r % 96;
        v = lfp_w[i * 9216 + k * 96 + n];
    } else if (idx < WOFF_DOWN) {              // UP: 3 x [384n][96k], src [96][384]
        int t = idx - WOFF_UP, j = t / 36864, r = t % 36864, n = r / 96, k = r % 96;
        const float* src = (j == 0) ? m0_w1 : (ms_w1 + (size_t)(j - 1) * 96 * 384);
        v = src[k * 384 + n];
    } else if (idx < WOFF_HEAD) {              // DOWN: 3 x [96n][384k], src [384][96]
        int t = idx - WOFF_DOWN, j = t / 36864, r = t % 36864, n = r / 384, k = r % 384;
        const float* src = (j == 0) ? m0_w2 : (ms_w2 + (size_t)(j - 1) * 384 * 96);
        v = src[k * 96 + n];
    } else {                                   // HEAD: [256n][96k], src [96][256]
        int t = idx - WOFF_HEAD, n = t / 96, k = t % 96;
        v = pp_w[k * 256 + n];
    }
    __nv_bfloat16 hi = __float2bfloat16(v);
    __nv_bfloat16 lo = __float2bfloat16(v - __bfloat162float(hi));
    g_whi[idx] = hi;
    g_wlo[idx] = lo;
}

// =============== fused MLP: f += bn(gelu(f@W1 + b1) @ W2) ===============
// CTA = 128 points. Hidden (384) processed in 4 slices of 96; hidden tile lives
// only in registers + smem. 256 threads = 8 warps (2M x 4N), warp tile 64x24.
#define AS   20                    // smem row stride in u32 per 32-k chunk
#define CHP  (128 * AS)            // u32 per chunk-plane for A/H (2560)
#define WCHP (96 * AS)             // u32 per chunk-plane for W  (1920)
#define OFF_H  (3 * 2 * CHP)       // 15360
#define OFF_W1 (OFF_H + 3 * 2 * CHP)          // 30720
#define OFF_W2 (OFF_W1 + 3 * 2 * WCHP)        // 42240
#define FUSED_SMEM ((OFF_W2 + 3 * 2 * WCHP) * 4)   // 215040 B

__global__ void __launch_bounds__(256, 1) fused_mlp(
    const float* __restrict__ F,
    const __nv_bfloat16* __restrict__ W1h, const __nv_bfloat16* __restrict__ W1l,   // [384][96]
    const __nv_bfloat16* __restrict__ W2h, const __nv_bfloat16* __restrict__ W2l,   // [96][384]
    const float* __restrict__ b1,
    const float* __restrict__ bng, const float* __restrict__ bnb,
    float* __restrict__ Fout)
{
    extern __shared__ uint32_t sm[];
    const uint32_t sb = smem_u32(sm);

    const int tid = threadIdx.x, wid = tid >> 5, lane = tid & 31;
    const int g = lane >> 2, t = lane & 3;
    const int warp_m = wid >> 2, warp_n = wid & 3;
    const int m0 = blockIdx.x * 128;

    const uint32_t aoff = ((warp_m * 64 + (lane & 7) + ((lane >> 3) & 1) * 8) * AS + (lane >> 4) * 4) * 4;
    const uint32_t boff = ((warp_n * 24 + (lane & 7)) * AS + (lane >> 3) * 4) * 4;

    // ---- load f tile [128 x 96], split hi/lo, chunked smem layout ----
#pragma unroll
    for (int it = 0; it < 12; it++) {
        const int e = it * 256 + tid;
        const int row = e / 24, qq = e % 24, col = qq * 4;
        float4 v = *(const float4*)&F[(size_t)(m0 + row) * 96 + col];
        uint32_t h0, l0, h1, l1;
        split2(v.x, v.y, h0, l0);
        split2(v.z, v.w, h1, l1);
        const int chunk = col >> 5, q = (col & 31) >> 2;
        uint32_t* p = sm + chunk * 2 * CHP + row * AS + q * 2;
        *(uint2*)p         = make_uint2(h0, h1);
        *(uint2*)(p + CHP) = make_uint2(l0, l1);
    }

    float out[4][3][4] = {};

    // per-chunk GEMM: acc += A(aBase chunk) x W(wBase chunk), 3-mma hi/lo
    auto gemm_chunk = [&](uint32_t aHi, uint32_t wHi, float acc[4][3][4]) {
        const uint32_t aLo = aHi + CHP * 4;
        const uint32_t wLo = wHi + WCHP * 4;
        uint32_t bh[3][4], bl[3][4];
#pragma unroll
        for (int j = 0; j < 3; j++) {
            ldm_x4(bh[j], wHi + boff + j * 8 * AS * 4);
            ldm_x4(bl[j], wLo + boff + j * 8 * AS * 4);
        }
#pragma unroll
        for (int ks = 0; ks < 2; ks++) {
#pragma unroll
            for (int i = 0; i < 4; i++) {
                uint32_t ah[4], al[4];
                ldm_x4(ah, aHi + aoff + (i * 16 * AS + ks * 8) * 4);
                ldm_x4(al, aLo + aoff + (i * 16 * AS + ks * 8) * 4);
#pragma unroll
                for (int j = 0; j < 3; j++) {
                    mma16816(acc[i][j], ah, &bh[j][ks * 2]);
                    mma16816(acc[i][j], ah, &bl[j][ks * 2]);
                    mma16816(acc[i][j], al, &bh[j][ks * 2]);
                }
            }
        }
    };

    for (int s = 0; s < 4; s++) {
        // ---- stage W1 slice s [96n x 96k] and W2 slice s [96n x 96k] ----
#pragma unroll
        for (int e = tid; e < 96 * 12; e += 256) {
            const int row = e / 12, qu = e % 12;
            const int chunk = qu >> 2, q4 = (qu & 3) * 4;
            {
                const size_t gi = (size_t)(s * 96 + row) * 96 + qu * 8;
                uint4 vh = *(const uint4*)&W1h[gi];
                uint4 vl = *(const uint4*)&W1l[gi];
                uint32_t* p = sm + OFF_W1 + chunk * 2 * WCHP + row * AS + q4;
                *(uint4*)p          = vh;
                *(uint4*)(p + WCHP) = vl;
            }
            {
                const size_t gi = (size_t)row * 384 + s * 96 + qu * 8;
                uint4 vh = *(const uint4*)&W2h[gi];
                uint4 vl = *(const uint4*)&W2l[gi];
                uint32_t* p = sm + OFF_W2 + chunk * 2 * WCHP + row * AS + q4;
                *(uint4*)p          = vh;
                *(uint4*)(p + WCHP) = vl;
            }
        }
        __syncthreads();   // W staged; previous slice's H readers done

        // ---- GEMM1: hid = f @ W1[s]  (128 x 96, k=96) ----
        float hid[4][3][4] = {};
#pragma unroll
        for (int kc = 0; kc < 3; kc++)
            gemm_chunk(sb + kc * 2 * CHP * 4, sb + (OFF_W1 + kc * 2 * WCHP) * 4, hid);

        // ---- bias + gelu, split, store H tile to smem ----
#pragma unroll
        for (int i = 0; i < 4; i++) {
            const int rm = warp_m * 64 + i * 16 + g;
#pragma unroll
            for (int j = 0; j < 3; j++) {
                const int nn = warp_n * 24 + j * 8 + t * 2;
                const float b0 = b1[s * 96 + nn], b1v = b1[s * 96 + nn + 1];
                float v0 = gelu_exact(hid[i][j][0] + b0);
                float v1 = gelu_exact(hid[i][j][1] + b1v);
                float v2 = gelu_exact(hid[i][j][2] + b0);
                float v3 = gelu_exact(hid[i][j][3] + b1v);
                uint32_t h01, l01, h23, l23;
                split2(v0, v1, h01, l01);
                split2(v2, v3, h23, l23);
                const int chunk = nn >> 5, q2 = (nn & 31) >> 1;
                uint32_t* p = sm + OFF_H + chunk * 2 * CHP;
                p[rm * AS + q2]             = h01;
                p[CHP + rm * AS + q2]       = l01;
                p[(rm + 8) * AS + q2]       = h23;
                p[CHP + (rm + 8) * AS + q2] = l23;
            }
        }
        __syncthreads();   // H visible

        // ---- GEMM2 partial: out += H @ W2[:, s*96:(s+1)*96] ----
#pragma unroll
        for (int kc = 0; kc < 3; kc++)
            gemm_chunk(sb + (OFF_H + kc * 2 * CHP) * 4, sb + (OFF_W2 + kc * 2 * WCHP) * 4, out);

        __syncthreads();   // done reading H & W for this slice
    }

    // ---- epilogue: f += out * bng + bnb ----
#pragma unroll
    for (int i = 0; i < 4; i++) {
        const int rm = m0 + warp_m * 64 + i * 16 + g;
#pragma unroll
        for (int j = 0; j < 3; j++) {
            const int n = warp_n * 24 + j * 8 + t * 2;
            const float s0 = bng[n], s1 = bng[n + 1];
            const float q0 = bnb[n], q1 = bnb[n + 1];
            float* p0 = &Fout[(size_t)rm * 96 + n];
            float* p1 = &Fout[(size_t)(rm + 8) * 96 + n];
            float2 c0 = *(float2*)p0;
            float2 c1 = *(float2*)p1;
            *(float2*)p0 = make_float2(c0.x + out[i][j][0] * s0 + q0,
                                       c0.y + out[i][j][1] * s1 + q1);
            *(float2*)p1 = make_float2(c1.x + out[i][j][2] * s0 + q0,
                                       c1.y + out[i][j][3] * s1 + q1);
        }
    }
}

// =============== HMMA GEMM (standalone, for LFP proj + head) ===============
// EPI: 0 plain.  ABN: a = a*gA[k]+bA[k] on load.
template <int EPI, bool ABN, int NT, int KTOT>
__global__ void __launch_bounds__(256, 2) hmma_gemm(
    const float* __restrict__ A,
    const __nv_bfloat16* __restrict__ Whi, const __nv_bfloat16* __restrict__ Wlo,
    float* __restrict__ C,
    const float* __restrict__ e1, const float* __restrict__ e2,
    const float* __restrict__ gA, const float* __restrict__ bA,
    int Nc)
{
    constexpr int WN   = NT / 4;
    constexpr int NTL  = WN / 8;
    constexpr int NC   = KTOT / 32;
    constexpr int ASZ  = 128 * AS;
    constexpr int BSZ  = NT * AS;
    constexpr int BUFU = 2 * ASZ + 2 * BSZ;

    extern __shared__ uint32_t sm[];
    const uint32_t sb = smem_u32(sm);

    const int tid = threadIdx.x, wid = tid >> 5, lane = tid & 31;
    const int g = lane >> 2, t = lane & 3;
    const int warp_m = wid >> 2, warp_n = wid & 3;
    const int m0 = blockIdx.y * 128, n0 = blockIdx.x * NT;

    float acc[4][NTL][4] = {};
    const float* Ablk = A + (size_t)m0 * KTOT;

    const uint32_t aoff = ((warp_m * 64 + (lane & 7) + ((lane >> 3) & 1) * 8) * AS + (lane >> 4) * 4) * 4;
    const uint32_t boff = ((warp_n * WN + (lane & 7)) * AS + (lane >> 3) * 4) * 4;

    auto load_chunk = [&](int kc, uint32_t* buf) {
        uint32_t* Ah = buf;
        uint32_t* Al = buf + ASZ;
        uint32_t* Bh = buf + 2 * ASZ;
        uint32_t* Bl = buf + 2 * ASZ + BSZ;
        const int kb = kc * 32;
#pragma unroll
        for (int it = 0; it < 4; it++) {
            const int e = it * 256 + tid;
            const int row = e >> 3, q = e & 7, col = q * 4;
            float4 v = *(const float4*)&Ablk[(size_t)row * KTOT + kb + col];
            if (ABN) {
                const int k = kb + col;
                v.x = v.x * gA[k]     + bA[k];
                v.y = v.y * gA[k + 1] + bA[k + 1];
                v.z = v.z * gA[k + 2] + bA[k + 2];
                v.w = v.w * gA[k + 3] + bA[k + 3];
            }
            uint32_t h0, l0, h1, l1;
            split2(v.x, v.y, h0, l0);
            split2(v.z, v.w, h1, l1);
            const int si = row * AS + q * 2;
            *(uint2*)&Ah[si] = make_uint2(h0, h1);
            *(uint2*)&Al[si] = make_uint2(l0, l1);
        }
#pragma unroll
        for (int e = tid; e < NT * 4; e += 256) {
            const int row = e >> 2, q = e & 3;
            const size_t gi = (size_t)(n0 + row) * KTOT + kb + q * 8;
            uint4 vh = *(const uint4*)&Whi[gi];
            uint4 vl = *(const uint4*)&Wlo[gi];
            const int si = row * AS + q * 4;
            *(uint2*)&Bh[si]     = make_uint2(vh.x, vh.y);
            *(uint2*)&Bh[si + 2] = make_uint2(vh.z, vh.w);
            *(uint2*)&Bl[si]     = make_uint2(vl.x, vl.y);
            *(uint2*)&Bl[si + 2] = make_uint2(vl.z, vl.w);
        }
    };

    auto compute = [&](uint32_t bufbase) {
        const uint32_t ahB = bufbase + aoff;
        const uint32_t alB = bufbase + ASZ * 4 + aoff;
        const uint32_t bhB = bufbase + 2 * ASZ * 4 + boff;
        const uint32_t blB = bufbase + (2 * ASZ + BSZ) * 4 + boff;
        uint32_t bh[NTL][4], bl[NTL][4];
#pragma unroll
        for (int j = 0; j < NTL; j++) {
            ldm_x4(bh[j], bhB + j * 8 * AS * 4);
            ldm_x4(bl[j], blB + j * 8 * AS * 4);
        }
#pragma unroll
        for (int ks = 0; ks < 2; ks++) {
#pragma unroll
            for (int i = 0; i < 4; i++) {
                uint32_t ah[4], al[4];
                ldm_x4(ah, ahB + (i * 16 * AS + ks * 8) * 4);
                ldm_x4(al, alB + (i * 16 * AS + ks * 8) * 4);
#pragma unroll
                for (int j = 0; j < NTL; j++) {
                    mma16816(acc[i][j], ah, &bh[j][ks * 2]);
                    mma16816(acc[i][j], ah, &bl[j][ks * 2]);
                    mma16816(acc[i][j], al, &bh[j][ks * 2]);
                }
            }
        }
    };

    load_chunk(0, sm);
    __syncthreads();
#pragma unroll
    for (int kc = 0; kc < NC; kc++) {
        if (kc + 1 < NC) load_chunk(kc + 1, sm + ((kc + 1) & 1) * BUFU);
        compute(sb + (uint32_t)(kc & 1) * BUFU * 4);
        __syncthreads();
    }

#pragma unroll
    for (int i = 0; i < 4; i++) {
        const int rm = m0 + warp_m * 64 + i * 16 + g;
#pragma unroll
        for (int j = 0; j < NTL; j++) {
            const int n = n0 + warp_n * WN + j * 8 + t * 2;
            float* d = acc[i][j];
            *(float2*)&C[(size_t)rm * Nc + n]       = make_float2(d[0], d[1]);
            *(float2*)&C[(size_t)(rm + 8) * Nc + n] = make_float2(d[2], d[3]);
        }
    }
}

// ---------------- neighbor embedding: per-edge MLP + 16-way max ----------------
__global__ void nbr_embed_kernel(
    const float* __restrict__ x, const float* __restrict__ xyz,
    const int* __restrict__ knn,
    const float* __restrict__ w1, const float* __restrict__ g1, const float* __restrict__ b1,
    const float* __restrict__ w2, const float* __restrict__ g2, const float* __restrict__ b2,
    const float* __restrict__ w3,
    const float* __restrict__ ng, const float* __restrict__ nb,
    float* __restrict__ f)
{
    __shared__ float sw1[7 * 16];
    __shared__ float sg1[16], sb1[16];
    __shared__ float sw2[16 * 32];
    __shared__ float sg2[32], sb2[32];
    __shared__ float sw3[32 * 96];
    __shared__ float sng[96], snb[96];

    const int tid = threadIdx.x;
    for (int i = tid; i < 7 * 16; i += 128) sw1[i] = w1[i];
    if (tid < 16) { sg1[tid] = g1[tid]; sb1[tid] = b1[tid]; }
    for (int i = tid; i < 16 * 32; i += 128) sw2[i] = w2[i];
    if (tid < 32) { sg2[tid] = g2[tid]; sb2[tid] = b2[tid]; }
    for (int i = tid; i < 32 * 96; i += 128) sw3[i] = w3[i];
    if (tid < 96) { sng[tid] = ng[tid]; snb[tid] = nb[tid]; }
    __syncthreads();

    const int n = blockIdx.x * 8 + (tid >> 4);
    const int k = tid & 15;
    const int j = knn[n * KNN + k];

    float v[7];
    v[0] = xyz[j * 3 + 0] - xyz[n * 3 + 0];
    v[1] = xyz[j * 3 + 1] - xyz[n * 3 + 1];
    v[2] = xyz[j * 3 + 2] - xyz[n * 3 + 2];
    v[3] = x[j * 4 + 0];
    v[4] = x[j * 4 + 1];
    v[5] = x[j * 4 + 2];
    v[6] = x[j * 4 + 3];

    float h1[16];
#pragma unroll
    for (int o = 0; o < 16; o++) {
        float s = 0.f;
#pragma unroll
        for (int i = 0; i < 7; i++) s += v[i] * sw1[i * 16 + o];
        h1[o] = gelu_exact(s * sg1[o] + sb1[o]);
    }
    float h2[32];
#pragma unroll
    for (int o = 0; o < 32; o++) {
        float s = 0.f;
#pragma unroll
        for (int i = 0; i < 16; i++) s += h1[i] * sw2[i * 32 + o];
        h2[o] = gelu_exact(s * sg2[o] + sb2[o]);
    }
#pragma unroll
    for (int ch = 0; ch < 3; ch++) {
        float acc[32];
#pragma unroll
        for (int o = 0; o < 32; o++) acc[o] = 0.f;
#pragma unroll
        for (int i = 0; i < 32; i++) {
            const float hv = h2[i];
#pragma unroll
            for (int o = 0; o < 32; o++) acc[o] += hv * sw3[i * 96 + ch * 32 + o];
        }
#pragma unroll
        for (int off = 8; off >= 1; off >>= 1) {
#pragma unroll
            for (int o = 0; o < 32; o++)
                acc[o] = fmaxf(acc[o], __shfl_xor_sync(0xffffffffu, acc[o], off));
        }
        if (k == 0) {
#pragma unroll
            for (int o = 0; o < 32; o++) {
                const int c = ch * 32 + o;
                f[(size_t)n * DCH + c] = acc[o] * sng[c] + snb[c];
            }
        }
    }
}

// ---------------- LFP edge: f += bn(max_k y[knn[n,k]] - y[n]) ----------------
__global__ void lfp_edge_kernel(
    const float* __restrict__ y, const int* __restrict__ knn,
    const float* __restrict__ g, const float* __restrict__ b,
    float* __restrict__ f)
{
    const int warp = (blockIdx.x * blockDim.x + threadIdx.x) >> 5;
    const int lane = threadIdx.x & 31;
    const int n = warp;

    float m0 = -3.402823466e38f, m1 = m0, m2 = m0;
#pragma unroll
    for (int k = 0; k < KNN; k++) {
        const int j = knn[n * KNN + k];
        const float* yr = y + (size_t)j * DCH;
        m0 = fmaxf(m0, yr[lane]);
        m1 = fmaxf(m1, yr[lane + 32]);
        m2 = fmaxf(m2, yr[lane + 64]);
    }
    const float* yn = y + (size_t)n * DCH;
    float* fn = f + (size_t)n * DCH;
    fn[lane]      += (m0 - yn[lane])      * g[lane]      + b[lane];
    fn[lane + 32] += (m1 - yn[lane + 32]) * g[lane + 32] + b[lane + 32];
    fn[lane + 64] += (m2 - yn[lane + 64]) * g[lane + 64] + b[lane + 64];
}

// ---------------- host ----------------
static inline int smem_bytes(int NT) { return 2 * (2 * 128 * AS + 2 * NT * AS) * 4; }

extern "C" void kernel_launch(void* const* d_in, const int* in_sizes, int n_in,
                              void* d_out, int out_size)
{
    const float* x      = (const float*)d_in[0];
    const float* xyz    = (const float*)d_in[1];
    const int*   knn    = (const int*)  d_in[2];
    const float* ne_w1  = (const float*)d_in[3];
    const float* ne_g1  = (const float*)d_in[4];
    const float* ne_b1  = (const float*)d_in[5];
    const float* ne_w2  = (const float*)d_in[6];
    const float* ne_g2  = (const float*)d_in[7];
    const float* ne_b2  = (const float*)d_in[8];
    const float* ne_w3  = (const float*)d_in[9];
    const float* nbr_g  = (const float*)d_in[10];
    const float* nbr_b  = (const float*)d_in[11];
    const float* m0_w1  = (const float*)d_in[12];
    const float* m0_b1  = (const float*)d_in[13];
    const float* m0_w2  = (const float*)d_in[14];
    const float* m0_g   = (const float*)d_in[15];
    const float* m0_b   = (const float*)d_in[16];
    const float* lfp_w  = (const float*)d_in[17];
    const float* lfp_g  = (const float*)d_in[18];
    const float* lfp_b  = (const float*)d_in[19];
    const float* ms_w1  = (const float*)d_in[20];
    const float* ms_b1  = (const float*)d_in[21];
    const float* ms_w2  = (const float*)d_in[22];
    const float* ms_g   = (const float*)d_in[23];
    const float* ms_b   = (const float*)d_in[24];
    const float* pp_g   = (const float*)d_in[25];
    const float* pp_b   = (const float*)d_in[26];
    const float* pp_w   = (const float*)d_in[27];
    float* out = (float*)d_out;

    float *f, *y;
    __nv_bfloat16 *whi, *wlo;
    cudaGetSymbolAddress((void**)&f, g_f);
    cudaGetSymbolAddress((void**)&y, g_y);
    cudaGetSymbolAddress((void**)&whi, g_whi);
    cudaGetSymbolAddress((void**)&wlo, g_wlo);

    const int SM96 = smem_bytes(96);
    const int SM64 = smem_bytes(64);
    cudaFuncSetAttribute(hmma_gemm<0, false, 96, 96>, cudaFuncAttributeMaxDynamicSharedMemorySize, SM96);
    cudaFuncSetAttribute(hmma_gemm<0, true, 64, 96>,  cudaFuncAttributeMaxDynamicSharedMemorySize, SM64);
    cudaFuncSetAttribute(fused_mlp, cudaFuncAttributeMaxDynamicSharedMemorySize, FUSED_SMEM);

    // weight pre-conversion (transpose + hi/lo split)
    conv_weights<<<(WTOTAL + 255) / 256, 256>>>(lfp_w, m0_w1, ms_w1, m0_w2, ms_w2, pp_w);

    // stage 1: neighbor embedding -> f [N,96]
    nbr_embed_kernel<<<NPTS / 8, 128>>>(
        x, xyz, knn, ne_w1, ne_g1, ne_b1, ne_w2, ne_g2, ne_b2, ne_w3, nbr_g, nbr_b, f);

    auto launch_mlp = [&](int j) {
        fused_mlp<<<NPTS / 128, 256, FUSED_SMEM>>>(
            f,
            whi + WOFF_UP + (size_t)j * 36864,   wlo + WOFF_UP + (size_t)j * 36864,
            whi + WOFF_DOWN + (size_t)j * 36864, wlo + WOFF_DOWN + (size_t)j * 36864,
            (j == 0) ? m0_b1 : (ms_b1 + (size_t)(j - 1) * HCH),
            (j == 0) ? m0_g  : (ms_g + (size_t)(j - 1) * DCH),
            (j == 0) ? m0_b  : (ms_b + (size_t)(j - 1) * DCH),
            f);
    };

    launch_mlp(0);
    for (int i = 0; i < 4; i++) {
        // y = f @ lfp_w[i]
        hmma_gemm<0, false, 96, 96><<<dim3(1, NPTS / 128), 256, SM96>>>(
            f, whi + WOFF_LFP + (size_t)i * 9216, wlo + WOFF_LFP + (size_t)i * 9216,
            y, nullptr, nullptr, nullptr, nullptr, DCH);
        // f += bn(max_k y[knn] - y)
        lfp_edge_kernel<<<NPTS / 8, 256>>>(y, knn, lfp_g + i * DCH, lfp_b + i * DCH, f);
        if (i & 1) launch_mlp(1 + i / 2);
    }

    // stage 4: out = bn(f) @ pp_w (BN folded into A load)
    hmma_gemm<0, true, 64, 96><<<dim3(HD / 64, NPTS / 128), 256, SM64>>>(
        f, whi + WOFF_HEAD, wlo + WOFF_HEAD,
        out, nullptr, nullptr, pp_g, pp_b, HD);
}